// round 16
// baseline (speedup 1.0000x reference)
#include <cuda_runtime.h>
#include <cuda_fp16.h>
#include <cstdint>

// Sizes
#define BSZ 512
#define HID 1024
#define NG  4096
#define INP 128
#define SEQ 96
#define NCH 16             // K chunks of 64 halfs
#define ATILEHF 4096       // halfs per A chunk tile (64 x 64)
#define ATILEB 8192        // bytes per A chunk tile
#define BTILEHF 4096       // halfs per B chunk tile (64 x 64)
#define BTILEB 8192        // bytes per B chunk tile
#define STAGEB (ATILEB + BTILEB)       // 16384
#define STG 3              // pipeline stages
#define SMEM_BYTES (STG * STAGEB)      // 49152 -> 4 CTAs/SM
#define PRE_SMEM 32768     // merged precompute smem (u0 branch dominates)

// Scratch (__device__ globals; no cudaMalloc allowed)
__device__ __align__(128) __half d_Weff[(size_t)NG * HID];    // [ntile*16+ch][64][64] swizzled
__device__ float d_beff[NG];                                  // permuted linear
__device__ float d_D0[(size_t)BSZ * NG];                      // step-0 correction [b][n']
__device__ float d_u0[BSZ * INP];
__device__ __align__(128) __half d_hbuf[2][(size_t)BSZ * HID]; // [(b>>6)*16+ch][64][64] swizzled
__device__ float d_cbuf[(size_t)BSZ * HID];                   // linear [b][j]
__device__ float d_part[(size_t)SEQ * 64 * BSZ];              // [t][ntile][b]

__device__ __forceinline__ float sigm(float x) { return 1.0f / (1.0f + __expf(-x)); }
__device__ __forceinline__ int permrow(int np) { return ((np & 3) << 10) | (np >> 2); }
__device__ __forceinline__ uint32_t sw128(uint32_t o) { return o ^ ((o >> 3) & 0x70); }

__device__ __forceinline__ uint32_t s2u(const void* p) {
    uint32_t a;
    asm("{ .reg .u64 t; cvta.to.shared.u64 t, %1; cvt.u32.u64 %0, t; }" : "=r"(a) : "l"(p));
    return a;
}
__device__ __forceinline__ void bulkcp(uint32_t dst, const void* src, uint32_t bytes, uint32_t mbar) {
    asm volatile(
        "cp.async.bulk.shared::cluster.global.mbarrier::complete_tx::bytes [%0], [%1], %2, [%3];"
        :: "r"(dst), "l"(src), "r"(bytes), "r"(mbar) : "memory");
}
__device__ __forceinline__ void mma16(float* c, const unsigned* a, const unsigned* b) {
    asm volatile(
        "mma.sync.aligned.m16n8k16.row.col.f32.f16.f16.f32 "
        "{%0,%1,%2,%3}, {%4,%5,%6,%7}, {%8,%9}, {%0,%1,%2,%3};"
        : "+f"(c[0]), "+f"(c[1]), "+f"(c[2]), "+f"(c[3])
        : "r"(a[0]), "r"(a[1]), "r"(a[2]), "r"(a[3]), "r"(b[0]), "r"(b[1]));
}
__device__ __forceinline__ void ldsm4(unsigned& r0, unsigned& r1, unsigned& r2, unsigned& r3,
                                      uint32_t a) {
    asm volatile("ldmatrix.sync.aligned.m8n8.x4.shared.b16 {%0,%1,%2,%3}, [%4];"
        : "=r"(r0), "=r"(r1), "=r"(r2), "=r"(r3) : "r"(a));
}
__device__ __forceinline__ void ldsm2(unsigned& r0, unsigned& r1, uint32_t a) {
    asm volatile("ldmatrix.sync.aligned.m8n8.x2.shared.b16 {%0,%1}, [%2];"
        : "=r"(r0), "=r"(r1) : "r"(a));
}
#define MBINIT(a, n) \
    asm volatile("mbarrier.init.shared.b64 [%0], %1;" :: "r"(a), "r"(n) : "memory")
#define MBEXPECT(a, n) \
    asm volatile("mbarrier.arrive.expect_tx.shared.b64 _, [%0], %1;" :: "r"(a), "r"(n) : "memory")
#define MBWAIT(a, ph) \
    asm volatile("{\n\t.reg .pred P;\n\tWL_%=: mbarrier.try_wait.parity.acquire.cta.shared::cta.b64 P, [%0], %1, 0x989680;\n\t@P bra.uni WD_%=;\n\tbra.uni WL_%=;\n\tWD_%=:\n\t}" \
                 :: "r"(a), "r"((uint32_t)(ph)) : "memory")
#define FPROXY() asm volatile("fence.proxy.async.shared::cta;" ::: "memory")

// ---------------- Merged precompute kernel ----------------
// Block dispatch (grid = 1408 x 256 threads, 32KB dyn smem):
//   [0, 1024)     weff   : W_eff fp16 tiles
//   [1024, 1280)  state  : h0 fp16 tiles + c0
//   [1280, 1344)  u0     : u0 = x0 - b_fc - h0·W_fc^T
//   [1344, 1408)  beff   : b_eff (coalesced, warp per gate row)
__global__ void __launch_bounds__(256, 1)
k_pre(const float* __restrict__ xt, const float* __restrict__ hid,
      const float* __restrict__ cell,
      const float* __restrict__ Wih, const float* __restrict__ Whh,
      const float* __restrict__ bih, const float* __restrict__ bhh,
      const float* __restrict__ Wfc, const float* __restrict__ bfc) {
    extern __shared__ float smf[];
    const int bid = blockIdx.x;
    const int tid = threadIdx.x;

    if (bid < 1024) {
        // ---- W_eff ----
        float (*wih_s)[INP] = (float(*)[INP])smf;   // 16 x 128 = 8KB
        int m = (bid & 3) * 256 + tid;
        int npb = (bid >> 2) * 16;
        for (int idx = tid; idx < 16 * INP; idx += 256)
            wih_s[idx >> 7][idx & 127] = Wih[permrow(npb + (idx >> 7)) * INP + (idx & 127)];
        __syncthreads();
        float acc[16];
        #pragma unroll
        for (int i = 0; i < 16; i++) acc[i] = Whh[(size_t)permrow(npb + i) * HID + m];
        for (int k = 0; k < INP; k++) {
            float w = Wfc[k * HID + m];
            #pragma unroll
            for (int i = 0; i < 16; i++) acc[i] += wih_s[i][k] * w;
        }
        #pragma unroll
        for (int i = 0; i < 16; i++) {
            int np = npb + i;
            int tile = (np >> 6) * 16 + (m >> 6);
            uint32_t bo = sw128((uint32_t)((np & 63) * 128 + (m & 63) * 2));
            *(__half*)((char*)d_Weff + (size_t)tile * BTILEB + bo) = __float2half_rn(acc[i]);
        }
    } else if (bid < 1280) {
        // ---- state init (8 elements per thread) ----
        int base = (bid - 1024) * 2048;
        #pragma unroll
        for (int r = 0; r < 8; r++) {
            int i = base + r * 256 + tid;
            int b = i >> 10, j = i & 1023;
            int tile = (b >> 6) * 16 + (j >> 6);          // 64-row A tiles
            uint32_t bo = sw128((uint32_t)((b & 63) * 128 + (j & 63) * 2));
            *(__half*)((char*)d_hbuf[0] + (size_t)tile * ATILEB + bo) = __float2half_rn(hid[i]);
            d_cbuf[i] = cell[i];
        }
    } else if (bid < 1344) {
        // ---- u0 ----
        float (*hs)[HID] = (float(*)[HID])smf;      // 8 x 1024 = 32KB
        const int bq = bid - 1280;
        const int lane = tid & 31, w = tid >> 5;
        for (int i = tid; i < 8 * HID; i += 256)
            hs[i >> 10][i & 1023] = hid[(size_t)(bq * 8 + (i >> 10)) * HID + (i & 1023)];
        __syncthreads();
        for (int k = w; k < INP; k += 8) {
            const float* wr = Wfc + (size_t)k * HID;
            float acc[8] = {0, 0, 0, 0, 0, 0, 0, 0};
            for (int i = lane; i < HID; i += 32) {
                float wv = wr[i];
                #pragma unroll
                for (int b8 = 0; b8 < 8; b8++) acc[b8] += hs[b8][i] * wv;
            }
            #pragma unroll
            for (int off = 16; off; off >>= 1)
                #pragma unroll
                for (int b8 = 0; b8 < 8; b8++)
                    acc[b8] += __shfl_xor_sync(0xffffffffu, acc[b8], off);
            if (lane == 0) {
                float bk = bfc[k];
                #pragma unroll
                for (int b8 = 0; b8 < 8; b8++) {
                    int b = bq * 8 + b8;
                    d_u0[b * INP + k] = xt[b * INP + k] - bk - acc[b8];
                }
            }
        }
    } else {
        // ---- b_eff (coalesced): warp handles 8 gate rows ----
        const int lane = tid & 31, w = tid >> 5;
        int np_base = (bid - 1344) * 64 + w * 8;
        #pragma unroll
        for (int i = 0; i < 8; i++) {
            int np = np_base + i;
            int r = permrow(np);
            float4 wv = *(const float4*)(Wih + (size_t)r * INP + lane * 4);
            float4 bv = *(const float4*)(bfc + lane * 4);
            float acc = wv.x * bv.x + wv.y * bv.y + wv.z * bv.z + wv.w * bv.w;
            #pragma unroll
            for (int off = 16; off; off >>= 1)
                acc += __shfl_xor_sync(0xffffffffu, acc, off);
            if (lane == 0) d_beff[np] = bih[r] + bhh[r] + acc;
        }
    }
}

// D0[b][n'] = u0[b]·W_ih[r]
__global__ void k_d0(const float* __restrict__ Wih) {
    __shared__ float us[4][INP];
    int tid = threadIdx.x;
    int bq = blockIdx.y;
    int np = blockIdx.x * 128 + tid;
    #pragma unroll
    for (int i = 0; i < 4; i++) us[i][tid] = d_u0[(bq * 4 + i) * INP + tid];
    __syncthreads();
    int r = permrow(np);
    float a0 = 0, a1 = 0, a2 = 0, a3 = 0;
    for (int k = 0; k < INP; k++) {
        float w = Wih[r * INP + k];
        a0 += us[0][k] * w; a1 += us[1][k] * w; a2 += us[2][k] * w; a3 += us[3][k] * w;
    }
    d_D0[(size_t)(bq * 4 + 0) * NG + np] = a0;
    d_D0[(size_t)(bq * 4 + 1) * NG + np] = a1;
    d_D0[(size_t)(bq * 4 + 2) * NG + np] = a2;
    d_D0[(size_t)(bq * 4 + 3) * NG + np] = a3;
}

// ---------------- Step kernel: tile 64M x 64N, 4 CTAs/SM, PDL ----------------
__global__ void __launch_bounds__(256, 4)
k_step(int t, int par, const float* __restrict__ Wfc) {
    extern __shared__ float sm[];
    __shared__ __align__(8) uint64_t mbf[STG];
    __shared__ float s_beff[64];
    __shared__ float s_w127[16];

    const int tid = threadIdx.x, lane = tid & 31, wid = tid >> 5;
    const int wm = wid & 1, wn = wid >> 1;        // 2 M-warps x 4 N-warps (32M x 16N each)
    const int gid = lane >> 2, tig = lane & 3;
    const int ntile = blockIdx.x, mtile = blockIdx.y;   // 64 x 8
    const int m0 = mtile * 64, n0 = ntile * 64;
    const int rlA = lane & 15;
    const int lhA = lane >> 4;
    const int rlB = lane & 7;
    const int lhB = (lane >> 3) & 1;

    // Preamble: only static data touched before the dependency sync.
    if (tid < 16) s_w127[tid] = Wfc[127 * HID + ntile * 16 + tid];
    if (tid < 64) s_beff[tid] = d_beff[n0 + tid];
    if (tid == 0) {
        #pragma unroll
        for (int s = 0; s < STG; s++) MBINIT(s2u(&mbf[s]), 2);
        FPROXY();
    }
    __syncthreads();

    const __half* Asrc = d_hbuf[par] + (size_t)mtile * 16 * ATILEHF;
    const __half* Bsrc = d_Weff + (size_t)ntile * 16 * BTILEHF;
    const uint32_t smu = s2u(sm);

    // Phase 1: B (static weights) — overlaps the previous step via PDL.
    if (tid == 0) {
        #pragma unroll
        for (int s = 0; s < STG; s++) {
            MBEXPECT(s2u(&mbf[s]), BTILEB);
            bulkcp(smu + s * STAGEB + ATILEB, Bsrc + s * BTILEHF, BTILEB, s2u(&mbf[s]));
        }
    }

    cudaTriggerProgrammaticLaunchCompletion();
    cudaGridDependencySynchronize();

    // Phase 2: A (h from previous step).
    if (tid == 0) {
        #pragma unroll
        for (int s = 0; s < STG; s++) {
            MBEXPECT(s2u(&mbf[s]), ATILEB);
            bulkcp(smu + s * STAGEB, Asrc + s * ATILEHF, ATILEB, s2u(&mbf[s]));
        }
    }

    float acc[2][2][4];
    #pragma unroll
    for (int a = 0; a < 2; a++)
        #pragma unroll
        for (int b = 0; b < 2; b++)
            #pragma unroll
            for (int c = 0; c < 4; c++) acc[a][b][c] = 0.f;

    for (int c = 0; c < NCH; c++) {
        const int q3 = c / 3;
        const int s = c - 3 * q3;                 // c % 3
        const int ph = q3 & 1;
        MBWAIT(s2u(&mbf[s]), ph);

        const uint32_t As = smu + s * STAGEB;
        const uint32_t Bs = As + ATILEB;
        #pragma unroll
        for (int k8 = 0; k8 < 32; k8 += 8) {
            const int u0 = k8 >> 2;
            unsigned a[2][4], b[2][2];
            #pragma unroll
            for (int mf = 0; mf < 2; mf++) {
                int row = wm * 32 + mf * 16 + rlA;
                uint32_t addr = As + row * 128 + ((((u0 + lhA) ^ (row & 7)) & 7) << 4);
                ldsm4(a[mf][0], a[mf][1], a[mf][2], a[mf][3], addr);
            }
            #pragma unroll
            for (int nf = 0; nf < 2; nf++) {
                int row = wn * 16 + nf * 8 + rlB;
                uint32_t addr = Bs + row * 128 + ((((u0 + lhB) ^ (row & 7)) & 7) << 4);
                ldsm2(b[nf][0], b[nf][1], addr);
            }
            #pragma unroll
            for (int mf = 0; mf < 2; mf++)
                #pragma unroll
                for (int nf = 0; nf < 2; nf++) mma16(acc[mf][nf], a[mf], b[nf]);
        }
        __syncthreads();
        if (tid == 0 && c + STG < NCH) {
            MBEXPECT(s2u(&mbf[s]), ATILEB);
            bulkcp(smu + s * STAGEB, Asrc + (c + STG) * ATILEHF, ATILEB, s2u(&mbf[s]));
            MBEXPECT(s2u(&mbf[s]), BTILEB);
            bulkcp(smu + s * STAGEB + ATILEB, Bsrc + (c + STG) * BTILEHF, BTILEB, s2u(&mbf[s]));
        }
    }

    // dump C tile (64 x 64, stride 68)
    #pragma unroll
    for (int mf = 0; mf < 2; mf++)
        #pragma unroll
        for (int nf = 0; nf < 2; nf++) {
            int row = wm * 32 + mf * 16 + gid;
            int col = wn * 16 + nf * 8 + 2 * tig;
            sm[row * 68 + col]           = acc[mf][nf][0];
            sm[row * 68 + col + 1]       = acc[mf][nf][1];
            sm[(row + 8) * 68 + col]     = acc[mf][nf][2];
            sm[(row + 8) * 68 + col + 1] = acc[mf][nf][3];
        }
    __syncthreads();

    // Fused LSTM epilogue: thread = (batch row bl, quarter jq of the 16 hidden units)
    {
        const int bl = tid >> 2, jq = tid & 3;
        const int b = m0 + bl;
        float* cb = d_cbuf + (size_t)b * HID + ntile * 16 + jq * 4;
        const float* csm = sm + bl * 68 + jq * 16;
        const float* d0p = d_D0 + (size_t)b * NG + n0 + jq * 16;
        char* hT = (char*)d_hbuf[par ^ 1] + (size_t)(mtile * 16 + (ntile >> 2)) * ATILEB;
        float partial = 0.f;

        float4 cold = *(const float4*)cb;
        float co[4] = {cold.x, cold.y, cold.z, cold.w};
        float hv[4];
        #pragma unroll
        for (int v = 0; v < 4; v++) {
            int g4 = v * 4;
            float gi = csm[g4]     + s_beff[jq * 16 + g4];
            float gf = csm[g4 + 1] + s_beff[jq * 16 + g4 + 1];
            float gg = csm[g4 + 2] + s_beff[jq * 16 + g4 + 2];
            float go = csm[g4 + 3] + s_beff[jq * 16 + g4 + 3];
            if (t == 0) {
                float4 dd = *(const float4*)(d0p + g4);
                gi += dd.x; gf += dd.y; gg += dd.z; go += dd.w;
            }
            float cn = sigm(gf) * co[v] + sigm(gi) * tanhf(gg);
            hv[v] = sigm(go) * tanhf(cn);
            co[v] = cn;
            partial += hv[v] * s_w127[jq * 4 + v];
        }
        *(float4*)cb = make_float4(co[0], co[1], co[2], co[3]);
        unsigned lo = (unsigned)__half_as_ushort(__float2half_rn(hv[0]))
                    | ((unsigned)__half_as_ushort(__float2half_rn(hv[1])) << 16);
        unsigned hi = (unsigned)__half_as_ushort(__float2half_rn(hv[2]))
                    | ((unsigned)__half_as_ushort(__float2half_rn(hv[3])) << 16);
        // 4 units = 8 bytes at the swizzled address (8B-aligned: sw128 flips bits 4-6 only)
        uint32_t bo = (uint32_t)(bl * 128 + (ntile & 3) * 32 + jq * 8);
        *(uint2*)(hT + sw128(bo)) = make_uint2(lo, hi);
        partial += __shfl_xor_sync(0xffffffffu, partial, 1);
        partial += __shfl_xor_sync(0xffffffffu, partial, 2);
        if (jq == 0) d_part[(size_t)t * (64 * BSZ) + ntile * BSZ + b] = partial;
    }
}

// out[b][t] = b_fc[127] + sum over 64 tiles
__global__ void k_reduce(float* __restrict__ out, const float* __restrict__ bfc) {
    int idx = blockIdx.x * 256 + threadIdx.x;
    if (idx >= BSZ * SEQ) return;
    int b = idx / SEQ, t = idx % SEQ;
    float s = bfc[127];
    #pragma unroll 8
    for (int nt = 0; nt < 64; nt++) s += d_part[(size_t)t * (64 * BSZ) + nt * BSZ + b];
    out[idx] = s;
}

extern "C" void kernel_launch(void* const* d_in, const int* in_sizes, int n_in,
                              void* d_out, int out_size) {
    const float* xt   = (const float*)d_in[0];
    const float* hid  = (const float*)d_in[1];
    const float* cell = (const float*)d_in[2];
    const float* Wih  = (const float*)d_in[3];
    const float* Whh  = (const float*)d_in[4];
    const float* bih  = (const float*)d_in[5];
    const float* bhh  = (const float*)d_in[6];
    const float* Wfc  = (const float*)d_in[7];
    const float* bfc  = (const float*)d_in[8];
    float* out = (float*)d_out;

    cudaFuncSetAttribute(k_step, cudaFuncAttributeMaxDynamicSharedMemorySize, SMEM_BYTES);
    cudaFuncSetAttribute(k_pre, cudaFuncAttributeMaxDynamicSharedMemorySize, PRE_SMEM);

    // Fused precompute (weff/state/u0/beff concurrent), then d0.
    k_pre<<<1408, 256, PRE_SMEM>>>(xt, hid, cell, Wih, Whh, bih, bhh, Wfc, bfc);
    k_d0<<<dim3(32, 128), 128>>>(Wih);

    // 96 dependent steps, PDL chained, 512 CTAs (4 per SM).
    cudaLaunchAttribute at[1];
    at[0].id = cudaLaunchAttributeProgrammaticStreamSerialization;
    at[0].val.programmaticStreamSerializationAllowed = 1;
    cudaLaunchConfig_t cfg = {};
    cfg.gridDim = dim3(64, 8);
    cfg.blockDim = dim3(256);
    cfg.dynamicSmemBytes = SMEM_BYTES;
    cfg.stream = 0;
    cfg.attrs = at;
    cfg.numAttrs = 1;
    for (int t = 0; t < SEQ; t++)
        cudaLaunchKernelEx(&cfg, k_step, t, t & 1, Wfc);

    k_reduce<<<192, 256>>>(out, bfc);
}

// round 17
// speedup vs baseline: 1.1256x; 1.1256x over previous
#include <cuda_runtime.h>
#include <cuda_fp16.h>
#include <cstdint>

// Sizes
#define BSZ 512
#define HID 1024
#define NG  4096
#define INP 128
#define SEQ 96
#define DCH 8              // K double-chunks of 128 halfs
#define ATILEHF 8192       // halfs per A chunk tile (128 x 64)
#define ATILEB 16384       // bytes per A chunk tile
#define BTILEHF 4096       // halfs per B chunk tile (64 x 64)
#define BTILEB 8192        // bytes per B chunk tile
#define STAGEB (2 * ATILEB + 2 * BTILEB)   // 49152 (double chunk)
#define STG 2              // pipeline stages
#define SMEM_BYTES (STG * STAGEB)          // 98304 -> 2 CTAs/SM
#define PRE_SMEM 32768     // merged precompute smem (u0 branch dominates)

// Scratch (__device__ globals; no cudaMalloc allowed)
__device__ __align__(128) __half d_Weff[(size_t)NG * HID];    // [ntile*16+ch][64][64] swizzled
__device__ float d_beff[NG];                                  // permuted linear
__device__ float d_D0[(size_t)BSZ * NG];                      // step-0 correction [b][n']
__device__ float d_u0[BSZ * INP];
__device__ __align__(128) __half d_hbuf[2][(size_t)BSZ * HID]; // [mtile*16+ch][128][64] swizzled
__device__ float d_cbuf[(size_t)BSZ * HID];                   // linear [b][j]
__device__ float d_part[(size_t)SEQ * 64 * BSZ];              // [t][ntile][b]

__device__ __forceinline__ float sigm(float x) { return 1.0f / (1.0f + __expf(-x)); }
__device__ __forceinline__ int permrow(int np) { return ((np & 3) << 10) | (np >> 2); }
__device__ __forceinline__ uint32_t sw128(uint32_t o) { return o ^ ((o >> 3) & 0x70); }

__device__ __forceinline__ uint32_t s2u(const void* p) {
    uint32_t a;
    asm("{ .reg .u64 t; cvta.to.shared.u64 t, %1; cvt.u32.u64 %0, t; }" : "=r"(a) : "l"(p));
    return a;
}
__device__ __forceinline__ void bulkcp(uint32_t dst, const void* src, uint32_t bytes, uint32_t mbar) {
    asm volatile(
        "cp.async.bulk.shared::cluster.global.mbarrier::complete_tx::bytes [%0], [%1], %2, [%3];"
        :: "r"(dst), "l"(src), "r"(bytes), "r"(mbar) : "memory");
}
__device__ __forceinline__ void mma16(float* c, const unsigned* a, const unsigned* b) {
    asm volatile(
        "mma.sync.aligned.m16n8k16.row.col.f32.f16.f16.f32 "
        "{%0,%1,%2,%3}, {%4,%5,%6,%7}, {%8,%9}, {%0,%1,%2,%3};"
        : "+f"(c[0]), "+f"(c[1]), "+f"(c[2]), "+f"(c[3])
        : "r"(a[0]), "r"(a[1]), "r"(a[2]), "r"(a[3]), "r"(b[0]), "r"(b[1]));
}
__device__ __forceinline__ void ldsm4(unsigned& r0, unsigned& r1, unsigned& r2, unsigned& r3,
                                      uint32_t a) {
    asm volatile("ldmatrix.sync.aligned.m8n8.x4.shared.b16 {%0,%1,%2,%3}, [%4];"
        : "=r"(r0), "=r"(r1), "=r"(r2), "=r"(r3) : "r"(a));
}
__device__ __forceinline__ void ldsm2(unsigned& r0, unsigned& r1, uint32_t a) {
    asm volatile("ldmatrix.sync.aligned.m8n8.x2.shared.b16 {%0,%1}, [%2];"
        : "=r"(r0), "=r"(r1) : "r"(a));
}
#define MBINIT(a, n) \
    asm volatile("mbarrier.init.shared.b64 [%0], %1;" :: "r"(a), "r"(n) : "memory")
#define MBEXPECT(a, n) \
    asm volatile("mbarrier.arrive.expect_tx.shared.b64 _, [%0], %1;" :: "r"(a), "r"(n) : "memory")
#define MBWAIT(a, ph) \
    asm volatile("{\n\t.reg .pred P;\n\tWL_%=: mbarrier.try_wait.parity.acquire.cta.shared::cta.b64 P, [%0], %1, 0x989680;\n\t@P bra.uni WD_%=;\n\tbra.uni WL_%=;\n\tWD_%=:\n\t}" \
                 :: "r"(a), "r"((uint32_t)(ph)) : "memory")
#define FPROXY() asm volatile("fence.proxy.async.shared::cta;" ::: "memory")

// ---------------- Merged precompute kernel ----------------
// Block dispatch (grid = 1408 x 256 threads, 32KB dyn smem):
//   [0, 1024)     weff : W_eff fp16 tiles
//   [1024, 1280)  state: h0 fp16 tiles + c0
//   [1280, 1344)  u0   : u0 = x0 - b_fc - h0·W_fc^T
//   [1344, 1408)  beff : b_eff (coalesced)
__global__ void __launch_bounds__(256, 1)
k_pre(const float* __restrict__ xt, const float* __restrict__ hid,
      const float* __restrict__ cell,
      const float* __restrict__ Wih, const float* __restrict__ Whh,
      const float* __restrict__ bih, const float* __restrict__ bhh,
      const float* __restrict__ Wfc, const float* __restrict__ bfc) {
    extern __shared__ float smf[];
    const int bid = blockIdx.x;
    const int tid = threadIdx.x;

    if (bid < 1024) {
        float (*wih_s)[INP] = (float(*)[INP])smf;
        int m = (bid & 3) * 256 + tid;
        int npb = (bid >> 2) * 16;
        for (int idx = tid; idx < 16 * INP; idx += 256)
            wih_s[idx >> 7][idx & 127] = Wih[permrow(npb + (idx >> 7)) * INP + (idx & 127)];
        __syncthreads();
        float acc[16];
        #pragma unroll
        for (int i = 0; i < 16; i++) acc[i] = Whh[(size_t)permrow(npb + i) * HID + m];
        for (int k = 0; k < INP; k++) {
            float w = Wfc[k * HID + m];
            #pragma unroll
            for (int i = 0; i < 16; i++) acc[i] += wih_s[i][k] * w;
        }
        #pragma unroll
        for (int i = 0; i < 16; i++) {
            int np = npb + i;
            int tile = (np >> 6) * 16 + (m >> 6);
            uint32_t bo = sw128((uint32_t)((np & 63) * 128 + (m & 63) * 2));
            *(__half*)((char*)d_Weff + (size_t)tile * BTILEB + bo) = __float2half_rn(acc[i]);
        }
    } else if (bid < 1280) {
        int base = (bid - 1024) * 2048;
        #pragma unroll
        for (int r = 0; r < 8; r++) {
            int i = base + r * 256 + tid;
            int b = i >> 10, j = i & 1023;
            int tile = (b >> 7) * 16 + (j >> 6);          // 128-row A tiles
            uint32_t bo = sw128((uint32_t)((b & 127) * 128 + (j & 63) * 2));
            *(__half*)((char*)d_hbuf[0] + (size_t)tile * ATILEB + bo) = __float2half_rn(hid[i]);
            d_cbuf[i] = cell[i];
        }
    } else if (bid < 1344) {
        float (*hs)[HID] = (float(*)[HID])smf;
        const int bq = bid - 1280;
        const int lane = tid & 31, w = tid >> 5;
        for (int i = tid; i < 8 * HID; i += 256)
            hs[i >> 10][i & 1023] = hid[(size_t)(bq * 8 + (i >> 10)) * HID + (i & 1023)];
        __syncthreads();
        for (int k = w; k < INP; k += 8) {
            const float* wr = Wfc + (size_t)k * HID;
            float acc[8] = {0, 0, 0, 0, 0, 0, 0, 0};
            for (int i = lane; i < HID; i += 32) {
                float wv = wr[i];
                #pragma unroll
                for (int b8 = 0; b8 < 8; b8++) acc[b8] += hs[b8][i] * wv;
            }
            #pragma unroll
            for (int off = 16; off; off >>= 1)
                #pragma unroll
                for (int b8 = 0; b8 < 8; b8++)
                    acc[b8] += __shfl_xor_sync(0xffffffffu, acc[b8], off);
            if (lane == 0) {
                float bk = bfc[k];
                #pragma unroll
                for (int b8 = 0; b8 < 8; b8++) {
                    int b = bq * 8 + b8;
                    d_u0[b * INP + k] = xt[b * INP + k] - bk - acc[b8];
                }
            }
        }
    } else {
        const int lane = tid & 31, w = tid >> 5;
        int np_base = (bid - 1344) * 64 + w * 8;
        #pragma unroll
        for (int i = 0; i < 8; i++) {
            int np = np_base + i;
            int r = permrow(np);
            float4 wv = *(const float4*)(Wih + (size_t)r * INP + lane * 4);
            float4 bv = *(const float4*)(bfc + lane * 4);
            float acc = wv.x * bv.x + wv.y * bv.y + wv.z * bv.z + wv.w * bv.w;
            #pragma unroll
            for (int off = 16; off; off >>= 1)
                acc += __shfl_xor_sync(0xffffffffu, acc, off);
            if (lane == 0) d_beff[np] = bih[r] + bhh[r] + acc;
        }
    }
}

// D0[b][n'] = u0[b]·W_ih[r]
__global__ void k_d0(const float* __restrict__ Wih) {
    __shared__ float us[4][INP];
    int tid = threadIdx.x;
    int bq = blockIdx.y;
    int np = blockIdx.x * 128 + tid;
    #pragma unroll
    for (int i = 0; i < 4; i++) us[i][tid] = d_u0[(bq * 4 + i) * INP + tid];
    __syncthreads();
    int r = permrow(np);
    float a0 = 0, a1 = 0, a2 = 0, a3 = 0;
    for (int k = 0; k < INP; k++) {
        float w = Wih[r * INP + k];
        a0 += us[0][k] * w; a1 += us[1][k] * w; a2 += us[2][k] * w; a3 += us[3][k] * w;
    }
    d_D0[(size_t)(bq * 4 + 0) * NG + np] = a0;
    d_D0[(size_t)(bq * 4 + 1) * NG + np] = a1;
    d_D0[(size_t)(bq * 4 + 2) * NG + np] = a2;
    d_D0[(size_t)(bq * 4 + 3) * NG + np] = a3;
}

// ---------------- Step kernel: tile 128M x 64N, 2 CTAs/SM, PDL, double-chunks ----------------
// Stage layout: [A0 16KB][A1 16KB][B0 8KB][B1 8KB] = 48KB; 2 stages.
__global__ void __launch_bounds__(256, 2)
k_step(int t, int par, const float* __restrict__ Wfc) {
    extern __shared__ float sm[];
    __shared__ __align__(8) uint64_t mbf[STG];
    __shared__ float s_beff[64];
    __shared__ float s_w127[16];

    const int tid = threadIdx.x, lane = tid & 31, wid = tid >> 5;
    const int wm = wid & 3, wn = wid >> 2;        // 4 M-warps x 2 N-warps (32M x 32N each)
    const int gid = lane >> 2, tig = lane & 3;
    const int ntile = blockIdx.x, mtile = blockIdx.y;   // 64 x 4
    const int m0 = mtile * 128, n0 = ntile * 64;
    const int rlA = lane & 15;
    const int lhA = lane >> 4;
    const int rlB = lane & 7;
    const int lhB = (lane >> 3) & 1;

    // Preamble: only static data touched before the dependency sync.
    if (tid < 16) s_w127[tid] = Wfc[127 * HID + ntile * 16 + tid];
    if (tid < 64) s_beff[tid] = d_beff[n0 + tid];
    if (tid == 0) {
        #pragma unroll
        for (int s = 0; s < STG; s++) MBINIT(s2u(&mbf[s]), 2);
        FPROXY();
    }
    __syncthreads();

    const __half* Asrc = d_hbuf[par] + (size_t)mtile * 16 * ATILEHF;
    const __half* Bsrc = d_Weff + (size_t)ntile * 16 * BTILEHF;
    const uint32_t smu = s2u(sm);

    // Phase 1: B (static weights, 16KB per stage) — overlaps the previous step via PDL.
    if (tid == 0) {
        #pragma unroll
        for (int s = 0; s < STG; s++) {
            MBEXPECT(s2u(&mbf[s]), 2 * BTILEB);
            bulkcp(smu + s * STAGEB + 2 * ATILEB, Bsrc + s * 2 * BTILEHF, 2 * BTILEB,
                   s2u(&mbf[s]));
        }
    }

    cudaTriggerProgrammaticLaunchCompletion();
    cudaGridDependencySynchronize();

    // Phase 2: A (h from previous step, 32KB per stage).
    if (tid == 0) {
        #pragma unroll
        for (int s = 0; s < STG; s++) {
            MBEXPECT(s2u(&mbf[s]), 2 * ATILEB);
            bulkcp(smu + s * STAGEB, Asrc + s * 2 * ATILEHF, 2 * ATILEB, s2u(&mbf[s]));
        }
    }

    float acc[2][4][4];
    #pragma unroll
    for (int a = 0; a < 2; a++)
        #pragma unroll
        for (int b = 0; b < 4; b++)
            #pragma unroll
            for (int c = 0; c < 4; c++) acc[a][b][c] = 0.f;

    for (int dc = 0; dc < DCH; dc++) {
        const int s = dc & 1;
        const int ph = (dc >> 1) & 1;
        MBWAIT(s2u(&mbf[s]), ph);

        #pragma unroll
        for (int half = 0; half < 2; half++) {
            const uint32_t As = smu + s * STAGEB + half * ATILEB;
            const uint32_t Bs = smu + s * STAGEB + 2 * ATILEB + half * BTILEB;
            #pragma unroll
            for (int k8 = 0; k8 < 32; k8 += 8) {
                const int u0 = k8 >> 2;
                unsigned a[2][4], b[4][2];
                #pragma unroll
                for (int mf = 0; mf < 2; mf++) {
                    int row = wm * 32 + mf * 16 + rlA;
                    uint32_t addr = As + row * 128 + ((((u0 + lhA) ^ (row & 7)) & 7) << 4);
                    ldsm4(a[mf][0], a[mf][1], a[mf][2], a[mf][3], addr);
                }
                #pragma unroll
                for (int nf = 0; nf < 4; nf++) {
                    int row = wn * 32 + nf * 8 + rlB;
                    uint32_t addr = Bs + row * 128 + ((((u0 + lhB) ^ (row & 7)) & 7) << 4);
                    ldsm2(b[nf][0], b[nf][1], addr);
                }
                #pragma unroll
                for (int mf = 0; mf < 2; mf++)
                    #pragma unroll
                    for (int nf = 0; nf < 4; nf++) mma16(acc[mf][nf], a[mf], b[nf]);
            }
        }
        __syncthreads();
        if (tid == 0 && dc + STG < DCH) {
            MBEXPECT(s2u(&mbf[s]), 2 * ATILEB);
            bulkcp(smu + s * STAGEB, Asrc + (dc + STG) * 2 * ATILEHF, 2 * ATILEB, s2u(&mbf[s]));
            MBEXPECT(s2u(&mbf[s]), 2 * BTILEB);
            bulkcp(smu + s * STAGEB + 2 * ATILEB, Bsrc + (dc + STG) * 2 * BTILEHF, 2 * BTILEB,
                   s2u(&mbf[s]));
        }
    }

    // dump C tile (128 x 64, stride 68)
    #pragma unroll
    for (int mf = 0; mf < 2; mf++)
        #pragma unroll
        for (int nf = 0; nf < 4; nf++) {
            int row = wm * 32 + mf * 16 + gid;
            int col = wn * 32 + nf * 8 + 2 * tig;
            sm[row * 68 + col]           = acc[mf][nf][0];
            sm[row * 68 + col + 1]       = acc[mf][nf][1];
            sm[(row + 8) * 68 + col]     = acc[mf][nf][2];
            sm[(row + 8) * 68 + col + 1] = acc[mf][nf][3];
        }
    __syncthreads();

    // Fused LSTM epilogue: thread = (batch row bl, half jh of the 16 hidden units)
    {
        const int bl = tid >> 1, jh = tid & 1;
        const int b = m0 + bl;
        float* cb = d_cbuf + (size_t)b * HID + ntile * 16 + jh * 8;
        const float* csm = sm + bl * 68 + jh * 32;
        const float* d0p = d_D0 + (size_t)b * NG + n0 + jh * 32;
        char* hT = (char*)d_hbuf[par ^ 1] + (size_t)(mtile * 16 + (ntile >> 2)) * ATILEB;
        float partial = 0.f;
        unsigned hp[4];

        #pragma unroll
        for (int q = 0; q < 2; q++) {               // 2 groups of 4 units
            float4 cold = *(const float4*)(cb + q * 4);
            float co[4] = {cold.x, cold.y, cold.z, cold.w};
            float hv[4];
            #pragma unroll
            for (int v = 0; v < 4; v++) {
                int g4 = q * 16 + v * 4;
                float gi = csm[g4]     + s_beff[jh * 32 + g4];
                float gf = csm[g4 + 1] + s_beff[jh * 32 + g4 + 1];
                float gg = csm[g4 + 2] + s_beff[jh * 32 + g4 + 2];
                float go = csm[g4 + 3] + s_beff[jh * 32 + g4 + 3];
                if (t == 0) {
                    float4 dd = *(const float4*)(d0p + g4);
                    gi += dd.x; gf += dd.y; gg += dd.z; go += dd.w;
                }
                float cn = sigm(gf) * co[v] + sigm(gi) * tanhf(gg);
                hv[v] = sigm(go) * tanhf(cn);
                co[v] = cn;
                partial += hv[v] * s_w127[jh * 8 + q * 4 + v];
            }
            *(float4*)(cb + q * 4) = make_float4(co[0], co[1], co[2], co[3]);
            unsigned lo = (unsigned)__half_as_ushort(__float2half_rn(hv[0]))
                        | ((unsigned)__half_as_ushort(__float2half_rn(hv[1])) << 16);
            unsigned hi = (unsigned)__half_as_ushort(__float2half_rn(hv[2]))
                        | ((unsigned)__half_as_ushort(__float2half_rn(hv[3])) << 16);
            hp[q * 2] = lo; hp[q * 2 + 1] = hi;
        }
        uint32_t bo = (uint32_t)(bl * 128 + (ntile & 3) * 32 + jh * 16);
        *(uint4*)(hT + sw128(bo)) = make_uint4(hp[0], hp[1], hp[2], hp[3]);
        partial += __shfl_xor_sync(0xffffffffu, partial, 1);
        if (jh == 0) d_part[(size_t)t * (64 * BSZ) + ntile * BSZ + b] = partial;
    }
}

// out[b][t] = b_fc[127] + sum over 64 tiles
__global__ void k_reduce(float* __restrict__ out, const float* __restrict__ bfc) {
    int idx = blockIdx.x * 256 + threadIdx.x;
    if (idx >= BSZ * SEQ) return;
    int b = idx / SEQ, t = idx % SEQ;
    float s = bfc[127];
    #pragma unroll 8
    for (int nt = 0; nt < 64; nt++) s += d_part[(size_t)t * (64 * BSZ) + nt * BSZ + b];
    out[idx] = s;
}

extern "C" void kernel_launch(void* const* d_in, const int* in_sizes, int n_in,
                              void* d_out, int out_size) {
    const float* xt   = (const float*)d_in[0];
    const float* hid  = (const float*)d_in[1];
    const float* cell = (const float*)d_in[2];
    const float* Wih  = (const float*)d_in[3];
    const float* Whh  = (const float*)d_in[4];
    const float* bih  = (const float*)d_in[5];
    const float* bhh  = (const float*)d_in[6];
    const float* Wfc  = (const float*)d_in[7];
    const float* bfc  = (const float*)d_in[8];
    float* out = (float*)d_out;

    cudaFuncSetAttribute(k_step, cudaFuncAttributeMaxDynamicSharedMemorySize, SMEM_BYTES);
    cudaFuncSetAttribute(k_pre, cudaFuncAttributeMaxDynamicSharedMemorySize, PRE_SMEM);

    // Fused precompute (weff/state/u0/beff concurrent), then d0.
    k_pre<<<1408, 256, PRE_SMEM>>>(xt, hid, cell, Wih, Whh, bih, bhh, Wfc, bfc);
    k_d0<<<dim3(32, 128), 128>>>(Wih);

    // 96 dependent steps, PDL chained, 256 CTAs (2 per SM).
    cudaLaunchAttribute at[1];
    at[0].id = cudaLaunchAttributeProgrammaticStreamSerialization;
    at[0].val.programmaticStreamSerializationAllowed = 1;
    cudaLaunchConfig_t cfg = {};
    cfg.gridDim = dim3(64, 4);
    cfg.blockDim = dim3(256);
    cfg.dynamicSmemBytes = SMEM_BYTES;
    cfg.stream = 0;
    cfg.attrs = at;
    cfg.numAttrs = 1;
    for (int t = 0; t < SEQ; t++)
        cudaLaunchKernelEx(&cfg, k_step, t, t & 1, Wfc);

    k_reduce<<<192, 256>>>(out, bfc);
}